// round 16
// baseline (speedup 1.0000x reference)
#include <cuda_runtime.h>
#include <cuda_bf16.h>
#include <math.h>
#include <stdint.h>

// ---------------- problem constants ----------------
#define T_TOK  2048
#define HID    4096
#define NH     32
#define DN     128   // qk_nope
#define DR     64    // qk_rope
#define DH     192   // qk_head
#define DV     128   // v_head
#define QL     1536  // q_lora
#define KVL    512   // kv_lora
#define QKV_N  (QL + KVL + DR)   // 2112 combined first-projection width

// ---------------- device scratch ----------------
__device__ float g_qakva [(size_t)T_TOK * QKV_N];
__device__ float g_q     [(size_t)T_TOK * NH * DH];
__device__ float g_kv    [(size_t)T_TOK * NH * (DN + DV)];
__device__ float g_s     [(size_t)NH * T_TOK * T_TOK];
__device__ float g_attn  [(size_t)T_TOK * NH * DV];
__device__ float g_rowsum[(size_t)NH * T_TOK];
__device__ float g_vt    [(size_t)NH * DV * T_TOK];
__device__ float g_hidr  [(size_t)T_TOK * HID];
__device__ float g_wqkva [(size_t)QKV_N * HID];
__device__ float g_wqb   [(size_t)NH * DH * QL];
__device__ float g_wkvb  [(size_t)NH * (DN + DV) * KVL];
__device__ float g_wo    [(size_t)HID * NH * DV];

// ---------------- helpers ----------------
__device__ __forceinline__ float round_tf32(float x) {
    float y;
    asm("cvt.rna.tf32.f32 %0, %1;" : "=f"(y) : "f"(x));
    return y;
}

__device__ __forceinline__ void mma_tf32(float* c, const uint32_t* a, const uint32_t* b) {
    asm volatile(
        "mma.sync.aligned.m16n8k8.row.col.f32.tf32.tf32.f32 "
        "{%0,%1,%2,%3}, {%4,%5,%6,%7}, {%8,%9}, {%0,%1,%2,%3};"
        : "+f"(c[0]), "+f"(c[1]), "+f"(c[2]), "+f"(c[3])
        : "r"(a[0]), "r"(a[1]), "r"(a[2]), "r"(a[3]), "r"(b[0]), "r"(b[1]));
}

__device__ __forceinline__ void ldsm_x4(uint32_t& r0, uint32_t& r1, uint32_t& r2,
                                        uint32_t& r3, uint32_t addr) {
    asm volatile("ldmatrix.sync.aligned.m8n8.x4.shared.b16 {%0,%1,%2,%3}, [%4];"
                 : "=r"(r0), "=r"(r1), "=r"(r2), "=r"(r3) : "r"(addr));
}

#define CP_ASYNC16(dst_u32, src_ptr, sz) \
    asm volatile("cp.async.cg.shared.global [%0], [%1], 16, %2;" \
        :: "r"(dst_u32), "l"(src_ptr), "r"(sz))
#define CP_COMMIT() asm volatile("cp.async.commit_group;" ::: "memory")
#define CP_WAIT1()  asm volatile("cp.async.wait_group 1;" ::: "memory")

// ---------------- elementwise tf32 rounding pass ----------------
__global__ void round_pass_kernel(const float* __restrict__ in, float* __restrict__ out,
                                  int n4)
{
    const int stride = gridDim.x * blockDim.x;
    for (int i = blockIdx.x * blockDim.x + threadIdx.x; i < n4; i += stride) {
        float4 v = ((const float4*)in)[i];
        v.x = round_tf32(v.x); v.y = round_tf32(v.y);
        v.z = round_tf32(v.z); v.w = round_tf32(v.w);
        ((float4*)out)[i] = v;
    }
}

// ---------------- fused round + transpose: in[R][C] -> out[C][R] ----------------
__global__ void transpose_round_kernel(const float* __restrict__ in,
                                       float* __restrict__ out, int R, int C)
{
    __shared__ float tile[32][33];
    const int c0 = blockIdx.x * 32;
    const int r0 = blockIdx.y * 32;
    const int tx = threadIdx.x;
#pragma unroll
    for (int i = threadIdx.y; i < 32; i += 8)
        tile[i][tx] = round_tf32(in[(size_t)(r0 + i) * C + c0 + tx]);
    __syncthreads();
#pragma unroll
    for (int i = threadIdx.y; i < 32; i += 8)
        out[(size_t)(c0 + i) * R + r0 + tx] = tile[tx][i];
}

// ---------------- transpose v slice of kv into g_vt ----------------
__global__ void vtrans_kernel()
{
    __shared__ float tile[32][33];
    const int t0  = blockIdx.x * 32;
    const int dv0 = blockIdx.y * 32;
    const int h   = blockIdx.z;
    const int tx  = threadIdx.x;
#pragma unroll
    for (int i = threadIdx.y; i < 32; i += 8)
        tile[i][tx] = g_kv[(size_t)(t0 + i) * (NH * (DN + DV)) + h * (DN + DV) + DN + dv0 + tx];
    __syncthreads();
#pragma unroll
    for (int i = threadIdx.y; i < 32; i += 8)
        g_vt[(size_t)h * DV * T_TOK + (size_t)(dv0 + i) * T_TOK + t0 + tx] = tile[tx][i];
}

// ---------------- tensor-core tf32 GEMM: BK=32, 3-stage cp.async, 2 CTAs/SM ----------------
// C[m,n] = alpha * sum_k A[m,k] * B[n,k]
// EPI: 0=raw store, 1=round, 2=rowsum-normalize+round, 3=rope k_pe cols (GEMM1),
//      4=rope pe / round nope per head (GEMM3)
// DUALB: k0>=KSPLIT reads B2. CLAMPK: K->min(K,m0+128), heavy-first within grid.
// moff: m-tile offset (128-row units).
#define NSTAGE 3
#define STG_WORDS 4096
#define GEMM_SMEM_BYTES (2 * NSTAGE * STG_WORDS * 4)
#define KSPLIT 128

template <bool SKIPN, bool CLAMPK, int EPI, bool DUALB>
__global__ __launch_bounds__(256, 2)
void tmma_gemm(const float* __restrict__ A, const float* __restrict__ B,
               float* __restrict__ C,
               int M, int N, int K, int lda, int ldb, int ldc,
               long long sA, long long sB, long long sC, float alpha,
               const float* __restrict__ B2, int ldb2, int zoff, int moff,
               const int* __restrict__ positions)
{
    extern __shared__ float smf[];

    const int tid  = threadIdx.x;
    const int wid  = tid >> 5;
    const int lane = tid & 31;
    const int g    = lane >> 2;
    const int tig  = lane & 3;

    const int wm = (wid >> 1) * 32;
    const int wn = (wid & 1) * 64;

    const int z  = blockIdx.z;
    int m0;
    if (CLAMPK) m0 = (moff + gridDim.y - 1 - blockIdx.y) * 128;   // heavy-first
    else        m0 = (moff + blockIdx.y) * 128;
    const int n0 = blockIdx.x * 128;

    if (SKIPN && n0 > m0 + 127) return;

    A += (size_t)z * sA;
    B += (size_t)z * sB;
    C += (size_t)z * sC;

    int Keff = K;
    if (CLAMPK) Keff = min(K, m0 + 128);
    const int nkt = Keff >> 5;

    const uint32_t a_sm = (uint32_t)__cvta_generic_to_shared(smf);
    const uint32_t b_sm = a_sm + NSTAGE * STG_WORDS * 4;

    const int lrow = tid >> 3;
    const int lchk = tid & 7;

    auto load_tile = [&](int kt) {
        const int st = kt % NSTAGE;
        const int k0 = kt << 5;
        const uint32_t asb = a_sm + (uint32_t)st * STG_WORDS * 4;
        const uint32_t bsb = b_sm + (uint32_t)st * STG_WORDS * 4;
#pragma unroll
        for (int i = 0; i < 4; i++) {
            const int row = i * 32 + lrow;
            const uint32_t dst = asb + (uint32_t)row * 128
                               + (uint32_t)((lchk ^ (row & 7)) << 4);
            const float* src = A + (size_t)(m0 + row) * lda + k0 + lchk * 4;
            CP_ASYNC16(dst, src, 16);
        }
        const float* Bp = B;
        int koff = k0, ldbp = ldb;
        if (DUALB && k0 >= KSPLIT) { Bp = B2; koff = k0 - KSPLIT; ldbp = ldb2; }
#pragma unroll
        for (int i = 0; i < 4; i++) {
            const int row = i * 32 + lrow;
            const bool in = (n0 + row < N);
            const uint32_t dst = bsb + (uint32_t)row * 128
                               + (uint32_t)((lchk ^ (row & 7)) << 4);
            const float* src = in ? (Bp + (size_t)(n0 + row) * ldbp + koff + lchk * 4) : Bp;
            CP_ASYNC16(dst, src, in ? 16 : 0);
        }
    };

    float acc[2][8][4];
#pragma unroll
    for (int mt = 0; mt < 2; mt++)
#pragma unroll
        for (int nt = 0; nt < 8; nt++)
#pragma unroll
            for (int r = 0; r < 4; r++) acc[mt][nt][r] = 0.0f;

    const int lr  = lane & 7;
    const int lhk = (lane >> 3) & 1;
    const int lhi = lane >> 4;

#pragma unroll
    for (int t = 0; t < NSTAGE - 1; t++) {
        if (t < nkt) load_tile(t);
        CP_COMMIT();
    }
    CP_WAIT1();
    __syncthreads();

    for (int kt = 0; kt < nkt; kt++) {
        if (kt + NSTAGE - 1 < nkt) load_tile(kt + NSTAGE - 1);
        CP_COMMIT();

        const int st = kt % NSTAGE;
        const uint32_t asb = a_sm + (uint32_t)st * STG_WORDS * 4;
        const uint32_t bsb = b_sm + (uint32_t)st * STG_WORDS * 4;

#pragma unroll
        for (int ks = 0; ks < 4; ks++) {
            uint32_t af[2][4];
#pragma unroll
            for (int mt = 0; mt < 2; mt++) {
                const int row = wm + mt * 16 + lhk * 8 + lr;
                const int chk = ks * 2 + lhi;
                const uint32_t addr = asb + (uint32_t)row * 128
                                    + (uint32_t)((chk ^ (row & 7)) << 4);
                ldsm_x4(af[mt][0], af[mt][1], af[mt][2], af[mt][3], addr);
            }
            uint32_t bf[8][2];
#pragma unroll
            for (int p = 0; p < 4; p++) {
                const int row = wn + p * 16 + lhi * 8 + lr;
                const int chk = ks * 2 + lhk;
                const uint32_t addr = bsb + (uint32_t)row * 128
                                    + (uint32_t)((chk ^ (row & 7)) << 4);
                ldsm_x4(bf[2 * p][0], bf[2 * p][1], bf[2 * p + 1][0], bf[2 * p + 1][1], addr);
            }
#pragma unroll
            for (int mt = 0; mt < 2; mt++)
#pragma unroll
                for (int nt = 0; nt < 8; nt++)
                    mma_tf32(acc[mt][nt], af[mt], bf[nt]);
        }

        CP_WAIT1();
        __syncthreads();
    }

    // ---- epilogue ----
#pragma unroll
    for (int mt = 0; mt < 2; mt++) {
        const int r0 = wm + mt * 16 + g;
        float inv0 = 1.0f, inv1 = 1.0f;
        if (EPI == 2) {
            inv0 = 1.0f / g_rowsum[(size_t)(z + zoff) * T_TOK + m0 + r0];
            inv1 = 1.0f / g_rowsum[(size_t)(z + zoff) * T_TOK + m0 + r0 + 8];
        }
        float pos0 = 0.0f, pos1 = 0.0f;
        if (EPI == 3 || EPI == 4) {
            pos0 = (float)positions[m0 + r0];
            pos1 = (float)positions[m0 + r0 + 8];
        }
#pragma unroll
        for (int nt = 0; nt < 8; nt++) {
            const int col = n0 + wn + nt * 8 + 2 * tig;
            if (col < N) {
                float o0 = alpha * acc[mt][nt][0], o1 = alpha * acc[mt][nt][1];
                float o2 = alpha * acc[mt][nt][2], o3 = alpha * acc[mt][nt][3];
                if (EPI == 1) {
                    o0 = round_tf32(o0); o1 = round_tf32(o1);
                    o2 = round_tf32(o2); o3 = round_tf32(o3);
                } else if (EPI == 2) {
                    o0 = round_tf32(o0 * inv0); o1 = round_tf32(o1 * inv0);
                    o2 = round_tf32(o2 * inv1); o3 = round_tf32(o3 * inv1);
                } else if (EPI == 3) {
                    if (col >= QL + KVL) {
                        const int i = (col - (QL + KVL)) >> 1;
                        const float inv = powf(10000.0f, -(float)(2 * i) / 64.0f);
                        float sn, cs;
                        sincosf(pos0 * inv, &sn, &cs);
                        float a = o0, b = o1;
                        o0 = round_tf32(a * cs - b * sn);
                        o1 = round_tf32(a * sn + b * cs);
                        sincosf(pos1 * inv, &sn, &cs);
                        a = o2; b = o3;
                        o2 = round_tf32(a * cs - b * sn);
                        o3 = round_tf32(a * sn + b * cs);
                    }
                } else if (EPI == 4) {
                    const int dh = col % DH;
                    if (dh >= DN) {
                        const int i = (dh - DN) >> 1;
                        const float inv = powf(10000.0f, -(float)(2 * i) / 64.0f);
                        float sn, cs;
                        sincosf(pos0 * inv, &sn, &cs);
                        float a = o0, b = o1;
                        o0 = round_tf32(a * cs - b * sn);
                        o1 = round_tf32(a * sn + b * cs);
                        sincosf(pos1 * inv, &sn, &cs);
                        a = o2; b = o3;
                        o2 = round_tf32(a * cs - b * sn);
                        o3 = round_tf32(a * sn + b * cs);
                    } else {
                        o0 = round_tf32(o0); o1 = round_tf32(o1);
                        o2 = round_tf32(o2); o3 = round_tf32(o3);
                    }
                }
                *(float2*)&C[(size_t)(m0 + r0) * ldc + col]     = make_float2(o0, o1);
                *(float2*)&C[(size_t)(m0 + r0 + 8) * ldc + col] = make_float2(o2, o3);
            }
        }
    }
}

// ---------------- fused dual rmsnorm over g_qakva ----------------
__global__ void rmsnorm2_kernel(const float* __restrict__ gq, const float* __restrict__ gkv)
{
    const int row = blockIdx.x;
    const int sec = blockIdx.y;
    const int off = sec ? QL : 0;
    const int w   = sec ? KVL : QL;
    const float* gg = sec ? gkv : gq;
    float* p = g_qakva + (size_t)row * QKV_N + off;
    __shared__ float red[256];
    float s = 0.0f;
    for (int c = threadIdx.x; c < w; c += 256) { float v = p[c]; s += v * v; }
    red[threadIdx.x] = s;
    __syncthreads();
    for (int o = 128; o > 0; o >>= 1) {
        if (threadIdx.x < o) red[threadIdx.x] += red[threadIdx.x + o];
        __syncthreads();
    }
    const float r = rsqrtf(red[0] / (float)w + 1e-6f);
    for (int c = threadIdx.x; c < w; c += 256)
        p[c] = round_tf32(p[c] * r * gg[c]);
}

// ---------------- single-pass causal softmax (q offset q0) ----------------
__global__ __launch_bounds__(256)
void softmax_kernel(const int* __restrict__ positions, int q0)
{
    const int q = blockIdx.x + q0;
    const int h = blockIdx.y;
    float* row = g_s + ((size_t)h * T_TOK + q) * T_TOK;
    const int pq = positions[q];
    const int jmax = ((q >> 7) + 1) << 7;
    __shared__ float red[256];
    const int tid = threadIdx.x;

    float vals[8];
    int cnt = 0;
    float m = -INFINITY;
    for (int j = tid; j < jmax; j += 256) {
        float v = (positions[j] <= pq) ? row[j] : -INFINITY;
        vals[cnt++] = v;
        m = fmaxf(m, v);
    }
    red[tid] = m;
    __syncthreads();
    for (int o = 128; o > 0; o >>= 1) {
        if (tid < o) red[tid] = fmaxf(red[tid], red[tid + o]);
        __syncthreads();
    }
    m = red[0];
    __syncthreads();

    float s = 0.0f;
    cnt = 0;
    for (int j = tid; j < jmax; j += 256) {
        const float e = __expf(vals[cnt++] - m);
        s += e;
        row[j] = round_tf32(e);
    }
    red[tid] = s;
    __syncthreads();
    for (int o = 128; o > 0; o >>= 1) {
        if (tid < o) red[tid] += red[tid + o];
        __syncthreads();
    }
    if (tid == 0) g_rowsum[(size_t)h * T_TOK + q] = red[0];
}

// ---------------- launcher ----------------
extern "C" void kernel_launch(void* const* d_in, const int* in_sizes, int n_in,
                              void* d_out, int out_size)
{
    const int*   positions = (const int*)  d_in[0];
    const float* hidden    = (const float*)d_in[1];
    const float* wq_a      = (const float*)d_in[2];
    const float* gq        = (const float*)d_in[3];
    const float* wq_b      = (const float*)d_in[4];
    const float* wkv_a     = (const float*)d_in[5];
    const float* gkv       = (const float*)d_in[6];
    const float* wkv_b     = (const float*)d_in[7];
    const float* wo        = (const float*)d_in[8];
    float* out = (float*)d_out;

    float *qakva, *q, *kv, *s, *attn, *vt;
    float *hidr, *wqkva, *wqb, *wkvb, *wor;
    cudaGetSymbolAddress((void**)&qakva, g_qakva);
    cudaGetSymbolAddress((void**)&q,     g_q);
    cudaGetSymbolAddress((void**)&kv,    g_kv);
    cudaGetSymbolAddress((void**)&s,     g_s);
    cudaGetSymbolAddress((void**)&attn,  g_attn);
    cudaGetSymbolAddress((void**)&vt,    g_vt);
    cudaGetSymbolAddress((void**)&hidr,  g_hidr);
    cudaGetSymbolAddress((void**)&wqkva, g_wqkva);
    cudaGetSymbolAddress((void**)&wqb,   g_wqb);
    cudaGetSymbolAddress((void**)&wkvb,  g_wkvb);
    cudaGetSymbolAddress((void**)&wor,   g_wo);

    static cudaStream_t s1 = nullptr, s2 = nullptr;
    static cudaEvent_t evRoot = nullptr, evP1 = nullptr, evP2 = nullptr, evF = nullptr;
    static cudaEvent_t evM = nullptr, evS1 = nullptr, evJ = nullptr;
    static bool attr_done = false;
    if (!attr_done) {
        cudaFuncSetAttribute(tmma_gemm<false,false,3,false>,
            cudaFuncAttributeMaxDynamicSharedMemorySize, GEMM_SMEM_BYTES);
        cudaFuncSetAttribute(tmma_gemm<false,false,4,false>,
            cudaFuncAttributeMaxDynamicSharedMemorySize, GEMM_SMEM_BYTES);
        cudaFuncSetAttribute(tmma_gemm<false,false,1,false>,
            cudaFuncAttributeMaxDynamicSharedMemorySize, GEMM_SMEM_BYTES);
        cudaFuncSetAttribute(tmma_gemm<true,false,0,true>,
            cudaFuncAttributeMaxDynamicSharedMemorySize, GEMM_SMEM_BYTES);
        cudaFuncSetAttribute(tmma_gemm<false,true,2,false>,
            cudaFuncAttributeMaxDynamicSharedMemorySize, GEMM_SMEM_BYTES);
        cudaFuncSetAttribute(tmma_gemm<false,false,0,false>,
            cudaFuncAttributeMaxDynamicSharedMemorySize, GEMM_SMEM_BYTES);
        cudaStreamCreateWithFlags(&s1, cudaStreamNonBlocking);
        cudaStreamCreateWithFlags(&s2, cudaStreamNonBlocking);
        cudaEventCreateWithFlags(&evRoot, cudaEventDisableTiming);
        cudaEventCreateWithFlags(&evP1, cudaEventDisableTiming);
        cudaEventCreateWithFlags(&evP2, cudaEventDisableTiming);
        cudaEventCreateWithFlags(&evF,  cudaEventDisableTiming);
        cudaEventCreateWithFlags(&evM,  cudaEventDisableTiming);
        cudaEventCreateWithFlags(&evS1, cudaEventDisableTiming);
        cudaEventCreateWithFlags(&evJ,  cudaEventDisableTiming);
        attr_done = true;
    }

    const float scale = 1.0f / sqrtf((float)DH);
    const dim3 blk(256);
    const int  shm = GEMM_SMEM_BYTES;
    const dim3 tblk(32, 8);
    const int  QT  = T_TOK / 128;    // 16 q-tiles
    const int  QTC = QT / 4;         // 4 q-tiles per chunk

    // ---- root fork ----
    cudaEventRecord(evRoot, 0);
    cudaStreamWaitEvent(s1, evRoot, 0);
    cudaStreamWaitEvent(s2, evRoot, 0);

    // ---- preprocessing fork ----
    round_pass_kernel<<<1024, 256>>>(hidden, hidr, (int)((size_t)T_TOK * HID / 4));
    transpose_round_kernel<<<dim3(QL/32, HID/32), tblk, 0, s1>>>(wq_a, wqkva, HID, QL);
    transpose_round_kernel<<<dim3((KVL+DR)/32, HID/32), tblk, 0, s1>>>(
        wkv_a, wqkva + (size_t)QL * HID, HID, KVL+DR);
    transpose_round_kernel<<<dim3(NH*DH/32, QL/32), tblk, 0, s2>>>(wq_b, wqb, QL, NH*DH);
    transpose_round_kernel<<<dim3(NH*(DN+DV)/32, KVL/32), tblk, 0, s2>>>(
        wkv_b, wkvb, KVL, NH*(DN+DV));
    transpose_round_kernel<<<dim3(HID/32, NH*DV/32), tblk, 0, s2>>>(wo, wor, NH*DV, HID);
    cudaEventRecord(evP1, s1);
    cudaEventRecord(evP2, s2);
    cudaStreamWaitEvent(0, evP1, 0);

    // 1. [qa | kva] = hidr @ wqkva^T  (EPI3: rope k_pe cols at store)
    tmma_gemm<false,false,3,false><<<dim3((QKV_N+127)/128, T_TOK/128, 1), blk, shm>>>(
        hidr, wqkva, qakva, T_TOK, QKV_N, HID, HID, HID, QKV_N, 0, 0, 0, 1.0f,
        nullptr, 0, 0, 0, positions);

    // 2. rmsnorm both sections -> rounded
    rmsnorm2_kernel<<<dim3(T_TOK, 2), 256>>>(gq, gkv);

    // fork: s1 runs GEMM4 + vtrans while main runs GEMM3(+rope)
    cudaEventRecord(evF, 0);
    cudaStreamWaitEvent(s1, evF, 0);
    cudaStreamWaitEvent(s1, evP2, 0);
    cudaStreamWaitEvent(0,  evP2, 0);

    // 4. (s1) kv = ckv_ln @ wkvb^T   (EPI1 rounds)
    tmma_gemm<false,false,1,false><<<dim3(NH*(DN+DV)/128, T_TOK/128, 1), blk, shm, s1>>>(
        qakva + QL, wkvb, kv, T_TOK, NH*(DN+DV), KVL, QKV_N, KVL, NH*(DN+DV),
        0, 0, 0, 1.0f, nullptr, 0, 0, 0, nullptr);
    vtrans_kernel<<<dim3(T_TOK/32, DV/32, NH), tblk, 0, s1>>>();

    // 3. q = qa_ln @ wqb^T  (EPI4: rope pe + round nope at store)
    tmma_gemm<false,false,4,false><<<dim3(NH*DH/128, T_TOK/128, 1), blk, shm>>>(
        qakva, wqb, q, T_TOK, NH*DH, QL, QKV_N, QL, NH*DH, 0, 0, 0, 1.0f,
        nullptr, 0, 0, 0, positions);

    // cross-sync: all chunks need q (main) and kv/vt (s1)
    cudaEventRecord(evM, 0);
    cudaEventRecord(evS1, s1);
    cudaStreamWaitEvent(0,  evS1, 0);
    cudaStreamWaitEvent(s1, evM, 0);

    // ---- attention + wo: 4 q-chunks, alternating streams, per-chunk pipeline
    //      scores -> softmax -> PV(+norm) -> wo. Chunk c covers q-tiles [c*QTC,(c+1)*QTC). ----
    for (int c = 0; c < 4; c++) {
        cudaStream_t st = (c & 1) ? s1 : (cudaStream_t)0;
        const int mo = c * QTC;                 // m-tile offset
        const int nx = (c + 1) * QTC;           // causal n-extent in tiles
        // scores = scale * q @ [k_nope | k_pe]^T
        tmma_gemm<true,false,0,true><<<dim3(nx, QTC, NH), blk, shm, st>>>(
            q, kv, s, T_TOK, T_TOK, DH, NH*DH, NH*(DN+DV), T_TOK,
            (long long)DH, (long long)(DN+DV), (long long)T_TOK*T_TOK, scale,
            qakva + QL + KVL, QKV_N, 0, mo, nullptr);
        // softmax
        softmax_kernel<<<dim3(QTC * 128, NH), 256, 0, st>>>(positions, mo * 128);
        // PV + row-normalize (K clamp, heavy-first)
        tmma_gemm<false,true,2,false><<<dim3(1, QTC, NH), blk, shm, st>>>(
            s, vt, attn, T_TOK, DV, T_TOK, T_TOK, T_TOK, NH*DV,
            (long long)T_TOK*T_TOK, (long long)DV*T_TOK, (long long)DV, 1.0f,
            nullptr, 0, 0, mo, nullptr);
        // wo for this q-range
        tmma_gemm<false,false,0,false><<<dim3(HID/128, QTC, 1), blk, shm, st>>>(
            attn, wor, out, T_TOK, HID, NH*DV, NH*DV, NH*DV, HID, 0, 0, 0, 1.0f,
            nullptr, 0, 0, mo, nullptr);
    }

    // join
    cudaEventRecord(evJ, s1);
    cudaStreamWaitEvent(0, evJ, 0);
}

// round 17
// speedup vs baseline: 1.0500x; 1.0500x over previous
#include <cuda_runtime.h>
#include <cuda_bf16.h>
#include <math.h>
#include <stdint.h>

// ---------------- problem constants ----------------
#define T_TOK  2048
#define HID    4096
#define NH     32
#define DN     128   // qk_nope
#define DR     64    // qk_rope
#define DH     192   // qk_head
#define DV     128   // v_head
#define QL     1536  // q_lora
#define KVL    512   // kv_lora
#define QKV_N  (QL + KVL + DR)   // 2112 combined first-projection width

// ---------------- device scratch ----------------
__device__ float g_qakva [(size_t)T_TOK * QKV_N];
__device__ float g_q     [(size_t)T_TOK * NH * DH];
__device__ float g_kv    [(size_t)T_TOK * NH * (DN + DV)];
__device__ float g_s     [(size_t)NH * T_TOK * T_TOK];
__device__ float g_attn  [(size_t)T_TOK * NH * DV];
__device__ float g_rowsum[(size_t)NH * T_TOK];
__device__ float g_vt    [(size_t)NH * DV * T_TOK];
__device__ float g_hidr  [(size_t)T_TOK * HID];
__device__ float g_wqkva [(size_t)QKV_N * HID];
__device__ float g_wqb   [(size_t)NH * DH * QL];
__device__ float g_wkvb  [(size_t)NH * (DN + DV) * KVL];
__device__ float g_wo    [(size_t)HID * NH * DV];

// ---------------- helpers ----------------
__device__ __forceinline__ float round_tf32(float x) {
    float y;
    asm("cvt.rna.tf32.f32 %0, %1;" : "=f"(y) : "f"(x));
    return y;
}

__device__ __forceinline__ void mma_tf32(float* c, const uint32_t* a, const uint32_t* b) {
    asm volatile(
        "mma.sync.aligned.m16n8k8.row.col.f32.tf32.tf32.f32 "
        "{%0,%1,%2,%3}, {%4,%5,%6,%7}, {%8,%9}, {%0,%1,%2,%3};"
        : "+f"(c[0]), "+f"(c[1]), "+f"(c[2]), "+f"(c[3])
        : "r"(a[0]), "r"(a[1]), "r"(a[2]), "r"(a[3]), "r"(b[0]), "r"(b[1]));
}

__device__ __forceinline__ void ldsm_x4(uint32_t& r0, uint32_t& r1, uint32_t& r2,
                                        uint32_t& r3, uint32_t addr) {
    asm volatile("ldmatrix.sync.aligned.m8n8.x4.shared.b16 {%0,%1,%2,%3}, [%4];"
                 : "=r"(r0), "=r"(r1), "=r"(r2), "=r"(r3) : "r"(addr));
}

#define CP_ASYNC16(dst_u32, src_ptr, sz) \
    asm volatile("cp.async.cg.shared.global [%0], [%1], 16, %2;" \
        :: "r"(dst_u32), "l"(src_ptr), "r"(sz))
#define CP_COMMIT() asm volatile("cp.async.commit_group;" ::: "memory")
#define CP_WAIT1()  asm volatile("cp.async.wait_group 1;" ::: "memory")

// ---------------- elementwise tf32 rounding pass ----------------
__global__ void round_pass_kernel(const float* __restrict__ in, float* __restrict__ out,
                                  int n4)
{
    const int stride = gridDim.x * blockDim.x;
    for (int i = blockIdx.x * blockDim.x + threadIdx.x; i < n4; i += stride) {
        float4 v = ((const float4*)in)[i];
        v.x = round_tf32(v.x); v.y = round_tf32(v.y);
        v.z = round_tf32(v.z); v.w = round_tf32(v.w);
        ((float4*)out)[i] = v;
    }
}

// ---------------- fused round + transpose: in[R][C] -> out[C][R] ----------------
__global__ void transpose_round_kernel(const float* __restrict__ in,
                                       float* __restrict__ out, int R, int C)
{
    __shared__ float tile[32][33];
    const int c0 = blockIdx.x * 32;
    const int r0 = blockIdx.y * 32;
    const int tx = threadIdx.x;
#pragma unroll
    for (int i = threadIdx.y; i < 32; i += 8)
        tile[i][tx] = round_tf32(in[(size_t)(r0 + i) * C + c0 + tx]);
    __syncthreads();
#pragma unroll
    for (int i = threadIdx.y; i < 32; i += 8)
        out[(size_t)(c0 + i) * R + r0 + tx] = tile[tx][i];
}

// ---------------- tensor-core tf32 GEMM: BK=32, 3-stage cp.async, 2 CTAs/SM ----------------
// C[m,n] = alpha * sum_k A[m,k] * B[n,k]
// EPI: 0=raw store, 1=round, 2=rowsum-normalize+round, 3=rope k_pe cols (GEMM1),
//      4=rope pe / round nope per head (GEMM3),
//      5=kv: round; v cols stored transposed into g_vt (fused vtrans)
// DUALB: k0>=KSPLIT reads B2. CLAMPK: K->min(K,m0+128), heavy-first within grid.
// moff: m-tile offset (128-row units).
#define NSTAGE 3
#define STG_WORDS 4096
#define GEMM_SMEM_BYTES (2 * NSTAGE * STG_WORDS * 4)
#define KSPLIT 128

template <bool SKIPN, bool CLAMPK, int EPI, bool DUALB>
__global__ __launch_bounds__(256, 2)
void tmma_gemm(const float* __restrict__ A, const float* __restrict__ B,
               float* __restrict__ C,
               int M, int N, int K, int lda, int ldb, int ldc,
               long long sA, long long sB, long long sC, float alpha,
               const float* __restrict__ B2, int ldb2, int zoff, int moff,
               const int* __restrict__ positions)
{
    extern __shared__ float smf[];

    const int tid  = threadIdx.x;
    const int wid  = tid >> 5;
    const int lane = tid & 31;
    const int g    = lane >> 2;
    const int tig  = lane & 3;

    const int wm = (wid >> 1) * 32;
    const int wn = (wid & 1) * 64;

    const int z  = blockIdx.z;
    int m0;
    if (CLAMPK) m0 = (moff + gridDim.y - 1 - blockIdx.y) * 128;   // heavy-first
    else        m0 = (moff + blockIdx.y) * 128;
    const int n0 = blockIdx.x * 128;

    if (SKIPN && n0 > m0 + 127) return;

    A += (size_t)z * sA;
    B += (size_t)z * sB;
    C += (size_t)z * sC;

    int Keff = K;
    if (CLAMPK) Keff = min(K, m0 + 128);
    const int nkt = Keff >> 5;

    const uint32_t a_sm = (uint32_t)__cvta_generic_to_shared(smf);
    const uint32_t b_sm = a_sm + NSTAGE * STG_WORDS * 4;

    const int lrow = tid >> 3;
    const int lchk = tid & 7;

    auto load_tile = [&](int kt) {
        const int st = kt % NSTAGE;
        const int k0 = kt << 5;
        const uint32_t asb = a_sm + (uint32_t)st * STG_WORDS * 4;
        const uint32_t bsb = b_sm + (uint32_t)st * STG_WORDS * 4;
#pragma unroll
        for (int i = 0; i < 4; i++) {
            const int row = i * 32 + lrow;
            const uint32_t dst = asb + (uint32_t)row * 128
                               + (uint32_t)((lchk ^ (row & 7)) << 4);
            const float* src = A + (size_t)(m0 + row) * lda + k0 + lchk * 4;
            CP_ASYNC16(dst, src, 16);
        }
        const float* Bp = B;
        int koff = k0, ldbp = ldb;
        if (DUALB && k0 >= KSPLIT) { Bp = B2; koff = k0 - KSPLIT; ldbp = ldb2; }
#pragma unroll
        for (int i = 0; i < 4; i++) {
            const int row = i * 32 + lrow;
            const bool in = (n0 + row < N);
            const uint32_t dst = bsb + (uint32_t)row * 128
                               + (uint32_t)((lchk ^ (row & 7)) << 4);
            const float* src = in ? (Bp + (size_t)(n0 + row) * ldbp + koff + lchk * 4) : Bp;
            CP_ASYNC16(dst, src, in ? 16 : 0);
        }
    };

    float acc[2][8][4];
#pragma unroll
    for (int mt = 0; mt < 2; mt++)
#pragma unroll
        for (int nt = 0; nt < 8; nt++)
#pragma unroll
            for (int r = 0; r < 4; r++) acc[mt][nt][r] = 0.0f;

    const int lr  = lane & 7;
    const int lhk = (lane >> 3) & 1;
    const int lhi = lane >> 4;

#pragma unroll
    for (int t = 0; t < NSTAGE - 1; t++) {
        if (t < nkt) load_tile(t);
        CP_COMMIT();
    }
    CP_WAIT1();
    __syncthreads();

    for (int kt = 0; kt < nkt; kt++) {
        if (kt + NSTAGE - 1 < nkt) load_tile(kt + NSTAGE - 1);
        CP_COMMIT();

        const int st = kt % NSTAGE;
        const uint32_t asb = a_sm + (uint32_t)st * STG_WORDS * 4;
        const uint32_t bsb = b_sm + (uint32_t)st * STG_WORDS * 4;

#pragma unroll
        for (int ks = 0; ks < 4; ks++) {
            uint32_t af[2][4];
#pragma unroll
            for (int mt = 0; mt < 2; mt++) {
                const int row = wm + mt * 16 + lhk * 8 + lr;
                const int chk = ks * 2 + lhi;
                const uint32_t addr = asb + (uint32_t)row * 128
                                    + (uint32_t)((chk ^ (row & 7)) << 4);
                ldsm_x4(af[mt][0], af[mt][1], af[mt][2], af[mt][3], addr);
            }
            uint32_t bf[8][2];
#pragma unroll
            for (int p = 0; p < 4; p++) {
                const int row = wn + p * 16 + lhi * 8 + lr;
                const int chk = ks * 2 + lhk;
                const uint32_t addr = bsb + (uint32_t)row * 128
                                    + (uint32_t)((chk ^ (row & 7)) << 4);
                ldsm_x4(bf[2 * p][0], bf[2 * p][1], bf[2 * p + 1][0], bf[2 * p + 1][1], addr);
            }
#pragma unroll
            for (int mt = 0; mt < 2; mt++)
#pragma unroll
                for (int nt = 0; nt < 8; nt++)
                    mma_tf32(acc[mt][nt], af[mt], bf[nt]);
        }

        CP_WAIT1();
        __syncthreads();
    }

    // ---- epilogue ----
#pragma unroll
    for (int mt = 0; mt < 2; mt++) {
        const int r0 = wm + mt * 16 + g;
        float inv0 = 1.0f, inv1 = 1.0f;
        if (EPI == 2) {
            inv0 = 1.0f / g_rowsum[(size_t)(z + zoff) * T_TOK + m0 + r0];
            inv1 = 1.0f / g_rowsum[(size_t)(z + zoff) * T_TOK + m0 + r0 + 8];
        }
        float pos0 = 0.0f, pos1 = 0.0f;
        if (EPI == 3 || EPI == 4) {
            pos0 = (float)positions[m0 + r0];
            pos1 = (float)positions[m0 + r0 + 8];
        }
#pragma unroll
        for (int nt = 0; nt < 8; nt++) {
            const int col = n0 + wn + nt * 8 + 2 * tig;
            if (col < N) {
                float o0 = alpha * acc[mt][nt][0], o1 = alpha * acc[mt][nt][1];
                float o2 = alpha * acc[mt][nt][2], o3 = alpha * acc[mt][nt][3];
                if (EPI == 1) {
                    o0 = round_tf32(o0); o1 = round_tf32(o1);
                    o2 = round_tf32(o2); o3 = round_tf32(o3);
                } else if (EPI == 2) {
                    o0 = round_tf32(o0 * inv0); o1 = round_tf32(o1 * inv0);
                    o2 = round_tf32(o2 * inv1); o3 = round_tf32(o3 * inv1);
                } else if (EPI == 3) {
                    if (col >= QL + KVL) {
                        const int i = (col - (QL + KVL)) >> 1;
                        const float inv = powf(10000.0f, -(float)(2 * i) / 64.0f);
                        float sn, cs;
                        sincosf(pos0 * inv, &sn, &cs);
                        float a = o0, b = o1;
                        o0 = round_tf32(a * cs - b * sn);
                        o1 = round_tf32(a * sn + b * cs);
                        sincosf(pos1 * inv, &sn, &cs);
                        a = o2; b = o3;
                        o2 = round_tf32(a * cs - b * sn);
                        o3 = round_tf32(a * sn + b * cs);
                    }
                } else if (EPI == 4) {
                    const int dh = col % DH;
                    if (dh >= DN) {
                        const int i = (dh - DN) >> 1;
                        const float inv = powf(10000.0f, -(float)(2 * i) / 64.0f);
                        float sn, cs;
                        sincosf(pos0 * inv, &sn, &cs);
                        float a = o0, b = o1;
                        o0 = round_tf32(a * cs - b * sn);
                        o1 = round_tf32(a * sn + b * cs);
                        sincosf(pos1 * inv, &sn, &cs);
                        a = o2; b = o3;
                        o2 = round_tf32(a * cs - b * sn);
                        o3 = round_tf32(a * sn + b * cs);
                    } else {
                        o0 = round_tf32(o0); o1 = round_tf32(o1);
                        o2 = round_tf32(o2); o3 = round_tf32(o3);
                    }
                } else if (EPI == 5) {
                    o0 = round_tf32(o0); o1 = round_tf32(o1);
                    o2 = round_tf32(o2); o3 = round_tf32(o3);
                    const int dh = col & 255;           // DN+DV = 256
                    if (dh >= DN) {
                        // v columns: transposed store into g_vt[h][dv][t]
                        const int h  = col >> 8;
                        const int dv = dh - DN;
                        float* vp = g_vt + ((size_t)h * DV + dv) * T_TOK;
                        vp[m0 + r0]             = o0;
                        vp[T_TOK + m0 + r0]     = o1;
                        vp[m0 + r0 + 8]         = o2;
                        vp[T_TOK + m0 + r0 + 8] = o3;
                        continue;   // no store into kv's v section (never read)
                    }
                }
                *(float2*)&C[(size_t)(m0 + r0) * ldc + col]     = make_float2(o0, o1);
                *(float2*)&C[(size_t)(m0 + r0 + 8) * ldc + col] = make_float2(o2, o3);
            }
        }
    }
}

// ---------------- fused dual rmsnorm over g_qakva ----------------
__global__ void rmsnorm2_kernel(const float* __restrict__ gq, const float* __restrict__ gkv)
{
    const int row = blockIdx.x;
    const int sec = blockIdx.y;
    const int off = sec ? QL : 0;
    const int w   = sec ? KVL : QL;
    const float* gg = sec ? gkv : gq;
    float* p = g_qakva + (size_t)row * QKV_N + off;
    __shared__ float red[256];
    float s = 0.0f;
    for (int c = threadIdx.x; c < w; c += 256) { float v = p[c]; s += v * v; }
    red[threadIdx.x] = s;
    __syncthreads();
    for (int o = 128; o > 0; o >>= 1) {
        if (threadIdx.x < o) red[threadIdx.x] += red[threadIdx.x + o];
        __syncthreads();
    }
    const float r = rsqrtf(red[0] / (float)w + 1e-6f);
    for (int c = threadIdx.x; c < w; c += 256)
        p[c] = round_tf32(p[c] * r * gg[c]);
}

// ---------------- single-pass causal softmax (q offset q0) ----------------
__global__ __launch_bounds__(256)
void softmax_kernel(const int* __restrict__ positions, int q0)
{
    const int q = blockIdx.x + q0;
    const int h = blockIdx.y;
    float* row = g_s + ((size_t)h * T_TOK + q) * T_TOK;
    const int pq = positions[q];
    const int jmax = ((q >> 7) + 1) << 7;
    __shared__ float red[256];
    const int tid = threadIdx.x;

    float vals[8];
    int cnt = 0;
    float m = -INFINITY;
    for (int j = tid; j < jmax; j += 256) {
        float v = (positions[j] <= pq) ? row[j] : -INFINITY;
        vals[cnt++] = v;
        m = fmaxf(m, v);
    }
    red[tid] = m;
    __syncthreads();
    for (int o = 128; o > 0; o >>= 1) {
        if (tid < o) red[tid] = fmaxf(red[tid], red[tid + o]);
        __syncthreads();
    }
    m = red[0];
    __syncthreads();

    float s = 0.0f;
    cnt = 0;
    for (int j = tid; j < jmax; j += 256) {
        const float e = __expf(vals[cnt++] - m);
        s += e;
        row[j] = round_tf32(e);
    }
    red[tid] = s;
    __syncthreads();
    for (int o = 128; o > 0; o >>= 1) {
        if (tid < o) red[tid] += red[tid + o];
        __syncthreads();
    }
    if (tid == 0) g_rowsum[(size_t)h * T_TOK + q] = red[0];
}

// ---------------- launcher ----------------
extern "C" void kernel_launch(void* const* d_in, const int* in_sizes, int n_in,
                              void* d_out, int out_size)
{
    const int*   positions = (const int*)  d_in[0];
    const float* hidden    = (const float*)d_in[1];
    const float* wq_a      = (const float*)d_in[2];
    const float* gq        = (const float*)d_in[3];
    const float* wq_b      = (const float*)d_in[4];
    const float* wkv_a     = (const float*)d_in[5];
    const float* gkv       = (const float*)d_in[6];
    const float* wkv_b     = (const float*)d_in[7];
    const float* wo        = (const float*)d_in[8];
    float* out = (float*)d_out;

    float *qakva, *q, *kv, *s, *attn, *vt;
    float *hidr, *wqkva, *wqb, *wkvb, *wor;
    cudaGetSymbolAddress((void**)&qakva, g_qakva);
    cudaGetSymbolAddress((void**)&q,     g_q);
    cudaGetSymbolAddress((void**)&kv,    g_kv);
    cudaGetSymbolAddress((void**)&s,     g_s);
    cudaGetSymbolAddress((void**)&attn,  g_attn);
    cudaGetSymbolAddress((void**)&vt,    g_vt);
    cudaGetSymbolAddress((void**)&hidr,  g_hidr);
    cudaGetSymbolAddress((void**)&wqkva, g_wqkva);
    cudaGetSymbolAddress((void**)&wqb,   g_wqb);
    cudaGetSymbolAddress((void**)&wkvb,  g_wkvb);
    cudaGetSymbolAddress((void**)&wor,   g_wo);

    static cudaStream_t s1 = nullptr, s2 = nullptr;
    static cudaEvent_t evRoot = nullptr, evP1 = nullptr, evP2 = nullptr, evF = nullptr;
    static cudaEvent_t evM = nullptr, evS1 = nullptr, evJ = nullptr;
    static bool attr_done = false;
    if (!attr_done) {
        cudaFuncSetAttribute(tmma_gemm<false,false,3,false>,
            cudaFuncAttributeMaxDynamicSharedMemorySize, GEMM_SMEM_BYTES);
        cudaFuncSetAttribute(tmma_gemm<false,false,4,false>,
            cudaFuncAttributeMaxDynamicSharedMemorySize, GEMM_SMEM_BYTES);
        cudaFuncSetAttribute(tmma_gemm<false,false,5,false>,
            cudaFuncAttributeMaxDynamicSharedMemorySize, GEMM_SMEM_BYTES);
        cudaFuncSetAttribute(tmma_gemm<true,false,0,true>,
            cudaFuncAttributeMaxDynamicSharedMemorySize, GEMM_SMEM_BYTES);
        cudaFuncSetAttribute(tmma_gemm<false,true,2,false>,
            cudaFuncAttributeMaxDynamicSharedMemorySize, GEMM_SMEM_BYTES);
        cudaFuncSetAttribute(tmma_gemm<false,false,0,false>,
            cudaFuncAttributeMaxDynamicSharedMemorySize, GEMM_SMEM_BYTES);
        cudaStreamCreateWithFlags(&s1, cudaStreamNonBlocking);
        cudaStreamCreateWithFlags(&s2, cudaStreamNonBlocking);
        cudaEventCreateWithFlags(&evRoot, cudaEventDisableTiming);
        cudaEventCreateWithFlags(&evP1, cudaEventDisableTiming);
        cudaEventCreateWithFlags(&evP2, cudaEventDisableTiming);
        cudaEventCreateWithFlags(&evF,  cudaEventDisableTiming);
        cudaEventCreateWithFlags(&evM,  cudaEventDisableTiming);
        cudaEventCreateWithFlags(&evS1, cudaEventDisableTiming);
        cudaEventCreateWithFlags(&evJ,  cudaEventDisableTiming);
        attr_done = true;
    }

    const float scale = 1.0f / sqrtf((float)DH);
    const dim3 blk(256);
    const int  shm = GEMM_SMEM_BYTES;
    const dim3 tblk(32, 8);
    const int  QT  = T_TOK / 128;    // 16 q-tiles
    const int  QTA = QT / 2;         // chain A: tiles 0..7

    // ---- root fork ----
    cudaEventRecord(evRoot, 0);
    cudaStreamWaitEvent(s1, evRoot, 0);
    cudaStreamWaitEvent(s2, evRoot, 0);

    // ---- preprocessing fork ----
    round_pass_kernel<<<1024, 256>>>(hidden, hidr, (int)((size_t)T_TOK * HID / 4));
    transpose_round_kernel<<<dim3(QL/32, HID/32), tblk, 0, s1>>>(wq_a, wqkva, HID, QL);
    transpose_round_kernel<<<dim3((KVL+DR)/32, HID/32), tblk, 0, s1>>>(
        wkv_a, wqkva + (size_t)QL * HID, HID, KVL+DR);
    transpose_round_kernel<<<dim3(NH*DH/32, QL/32), tblk, 0, s2>>>(wq_b, wqb, QL, NH*DH);
    transpose_round_kernel<<<dim3(NH*(DN+DV)/32, KVL/32), tblk, 0, s2>>>(
        wkv_b, wkvb, KVL, NH*(DN+DV));
    transpose_round_kernel<<<dim3(HID/32, NH*DV/32), tblk, 0, s2>>>(wo, wor, NH*DV, HID);
    cudaEventRecord(evP1, s1);
    cudaEventRecord(evP2, s2);
    cudaStreamWaitEvent(0, evP1, 0);

    // 1. [qa | kva] = hidr @ wqkva^T  (EPI3: rope k_pe cols at store)
    tmma_gemm<false,false,3,false><<<dim3((QKV_N+127)/128, T_TOK/128, 1), blk, shm>>>(
        hidr, wqkva, qakva, T_TOK, QKV_N, HID, HID, HID, QKV_N, 0, 0, 0, 1.0f,
        nullptr, 0, 0, 0, positions);

    // 2. rmsnorm both sections -> rounded
    rmsnorm2_kernel<<<dim3(T_TOK, 2), 256>>>(gq, gkv);

    // fork: s1 runs GEMM4 (with fused vtrans) while main runs GEMM3(+rope)
    cudaEventRecord(evF, 0);
    cudaStreamWaitEvent(s1, evF, 0);
    cudaStreamWaitEvent(s1, evP2, 0);
    cudaStreamWaitEvent(0,  evP2, 0);

    // 4. (s1) kv = ckv_ln @ wkvb^T   (EPI5: rounds; v cols -> g_vt transposed)
    tmma_gemm<false,false,5,false><<<dim3(NH*(DN+DV)/128, T_TOK/128, 1), blk, shm, s1>>>(
        qakva + QL, wkvb, kv, T_TOK, NH*(DN+DV), KVL, QKV_N, KVL, NH*(DN+DV),
        0, 0, 0, 1.0f, nullptr, 0, 0, 0, nullptr);

    // 3. q = qa_ln @ wqb^T  (EPI4: rope pe + round nope at store)
    tmma_gemm<false,false,4,false><<<dim3(NH*DH/128, T_TOK/128, 1), blk, shm>>>(
        qakva, wqb, q, T_TOK, NH*DH, QL, QKV_N, QL, NH*DH, 0, 0, 0, 1.0f,
        nullptr, 0, 0, 0, positions);

    // cross-sync: both chains need q (main) and kv/vt (s1)
    cudaEventRecord(evM, 0);
    cudaEventRecord(evS1, s1);
    cudaStreamWaitEvent(0,  evS1, 0);
    cudaStreamWaitEvent(s1, evM, 0);

    // ---- attention + wo pipelined by q-range: chain A (tiles 0..7) on main,
    //      chain B (tiles 8..15) on s1. ----
    for (int c = 0; c < 2; c++) {
        cudaStream_t st = c ? s1 : (cudaStream_t)0;
        const int mo = c * QTA;
        const int nx = c ? QT : QTA;
        // scores = scale * q @ [k_nope | k_pe]^T
        tmma_gemm<true,false,0,true><<<dim3(nx, QTA, NH), blk, shm, st>>>(
            q, kv, s, T_TOK, T_TOK, DH, NH*DH, NH*(DN+DV), T_TOK,
            (long long)DH, (long long)(DN+DV), (long long)T_TOK*T_TOK, scale,
            qakva + QL + KVL, QKV_N, 0, mo, nullptr);
        // softmax
        softmax_kernel<<<dim3(T_TOK/2, NH), 256, 0, st>>>(positions, mo * 128);
        // PV + row-normalize (K clamp, heavy-first)
        tmma_gemm<false,true,2,false><<<dim3(1, QTA, NH), blk, shm, st>>>(
            s, vt, attn, T_TOK, DV, T_TOK, T_TOK, T_TOK, NH*DV,
            (long long)T_TOK*T_TOK, (long long)DV*T_TOK, (long long)DV, 1.0f,
            nullptr, 0, 0, mo, nullptr);
        // wo for this q-range
        tmma_gemm<false,false,0,false><<<dim3(HID/128, QTA, 1), blk, shm, st>>>(
            attn, wor, out, T_TOK, HID, NH*DV, NH*DV, NH*DV, HID, 0, 0, 0, 1.0f,
            nullptr, 0, 0, mo, nullptr);
    }

    // join
    cudaEventRecord(evJ, s1);
    cudaStreamWaitEvent(0, evJ, 0);
}